// round 16
// baseline (speedup 1.0000x reference)
#include <cuda_runtime.h>
#include <cstdint>

#define N_NODES 100000
#define N_EDGES 1600000
#define HID 128
#define NUM_LAYERS 10
#define NUM_GRAPHS 64
#define NUM_CLASSES 2
#define TILE_R 32
#define TILES ((N_NODES + TILE_R - 1) / TILE_R)   // 3125
#define GRID_L 296                                 // 2 blocks/SM on 148 SMs
#define HSTR 132                                   // padded row stride (floats)

// ---------------- scratch (device globals; no runtime allocation) ----------------
__device__ __align__(16) float g_x[(size_t)N_NODES * HID];   // ping-pong buf A
__device__ __align__(16) float g_y[(size_t)N_NODES * HID];   // ping-pong buf B
__device__ int   g_deg[N_NODES];
__device__ int   g_rowptr[N_NODES + 1];
__device__ int   g_fill[N_NODES];
__device__ int   g_ssrc[N_EDGES];
__device__ int   g_bsums[256];
__device__ __align__(16) float g_pool[NUM_GRAPHS * HID];
__device__ float g_cnt[NUM_GRAPHS];
__device__ __align__(16) float g_cls[NUM_GRAPHS * HID];

// ---------------- CSR build ----------------
__global__ void zero_kernel() {
    int i = blockIdx.x * blockDim.x + threadIdx.x;
    if (i < N_NODES) g_deg[i] = 0;
    if (i < NUM_GRAPHS * HID) g_pool[i] = 0.f;
    if (i < NUM_GRAPHS) g_cnt[i] = 0.f;
}

__global__ void hist_kernel(const int* __restrict__ dst) {
    int e = blockIdx.x * blockDim.x + threadIdx.x;
    if (e < N_EDGES) atomicAdd(&g_deg[dst[e]], 1);
}

__global__ void scan1_kernel() {
    __shared__ int s[512];
    int tid = threadIdx.x;
    int i = blockIdx.x * 512 + tid;
    int v = (i < N_NODES) ? g_deg[i] : 0;
    s[tid] = v;
    __syncthreads();
    for (int off = 1; off < 512; off <<= 1) {
        int add = (tid >= off) ? s[tid - off] : 0;
        __syncthreads();
        s[tid] += add;
        __syncthreads();
    }
    if (i < N_NODES) g_rowptr[i] = s[tid] - v;
    if (tid == 511) g_bsums[blockIdx.x] = s[511];
}

__global__ void scan2_kernel(int nblk) {
    __shared__ int s[256];
    int tid = threadIdx.x;
    int v = (tid < nblk) ? g_bsums[tid] : 0;
    s[tid] = v;
    __syncthreads();
    for (int off = 1; off < 256; off <<= 1) {
        int add = (tid >= off) ? s[tid - off] : 0;
        __syncthreads();
        s[tid] += add;
        __syncthreads();
    }
    if (tid < nblk) g_bsums[tid] = s[tid] - v;
}

__global__ void scan3_kernel() {
    int i = blockIdx.x * blockDim.x + threadIdx.x;
    if (i < N_NODES) {
        int rp = g_rowptr[i] + g_bsums[i >> 9];
        g_rowptr[i] = rp;
        g_fill[i] = rp;
    }
    if (i == 0) g_rowptr[N_NODES] = N_EDGES;
}

__global__ void scatter_kernel(const int* __restrict__ src,
                               const int* __restrict__ dst) {
    int e = blockIdx.x * blockDim.x + threadIdx.x;
    if (e < N_EDGES) {
        int d = dst[e];
        int p = atomicAdd(&g_fill[d], 1);
        g_ssrc[p] = src[e];
    }
}

// ======== warp-specialized fused layer: gather warps || compute warps ============
// 296 persistent-style blocks, each strides ~11 tiles of 32 rows. Warps 4-7 fill
// buf[j&1] (CSR gather) while warps 0-3 run the 2-GEMM MLP on buf[(j-1)&1].
__global__ void __launch_bounds__(256, 2)
layer_kernel(const float* __restrict__ xin_ext,
             const float* __restrict__ eps,
             const float* __restrict__ W1, const float* __restrict__ b1,
             const float* __restrict__ W2, const float* __restrict__ b2,
             int layer) {
    __shared__ float Bs[2][TILE_R * HSTR];   // 2 x 16.9 KB

    int t = threadIdx.x;
    int w = t >> 5, lane = t & 31;
    int bid = blockIdx.x;
    int G = gridDim.x;

    const float* src = (layer == 0) ? xin_ext : ((layer & 1) ? g_y : g_x);
    float* dstbuf = (layer & 1) ? g_x : g_y;
    int add_h = (layer > 0) ? 1 : 0;
    float ep1 = 1.0f + eps[layer];
    const float4* xv = (const float4*)src;

    int M = (bid < TILES) ? ((TILES - bid + G - 1) / G) : 0;
    if (M == 0) return;  // (never for G=296 < TILES)

    int tx = t & 15, ty = (t & 127) >> 4;   // compute mapping: 16x8 threads
    int cb = tx * 8;                        // 8 cols per thread
    int rb = ty * 4;                        // 4 rows per thread

    for (int j = 0; j <= M; j++) {
        if (t >= 128) {
            // ---------------- gather warps: fill tile j ----------------
            if (j < M) {
                int row0 = (bid + j * G) * TILE_R;
                float* buf = Bs[j & 1];
                int gw = w - 4;   // 0..3
                for (int r = 0; r < 8; r++) {
                    int lr = gw * 8 + r;
                    int node = row0 + lr;
                    float4 a0 = make_float4(0.f, 0.f, 0.f, 0.f);
                    if (node < N_NODES) {
                        float4 b = __ldg(&xv[(size_t)node * 32 + lane]);
                        a0 = make_float4(b.x * ep1, b.y * ep1, b.z * ep1, b.w * ep1);
                        float4 a1 = make_float4(0.f, 0.f, 0.f, 0.f);
                        float4 a2 = a1, a3 = a1;
                        int s = g_rowptr[node], e = g_rowptr[node + 1];
                        int i = s;
                        for (; i + 4 <= e; i += 4) {
                            int s0 = g_ssrc[i], s1 = g_ssrc[i + 1];
                            int s2 = g_ssrc[i + 2], s3 = g_ssrc[i + 3];
                            float4 v0 = __ldg(&xv[(size_t)s0 * 32 + lane]);
                            float4 v1 = __ldg(&xv[(size_t)s1 * 32 + lane]);
                            float4 v2 = __ldg(&xv[(size_t)s2 * 32 + lane]);
                            float4 v3 = __ldg(&xv[(size_t)s3 * 32 + lane]);
                            a0.x += v0.x; a0.y += v0.y; a0.z += v0.z; a0.w += v0.w;
                            a1.x += v1.x; a1.y += v1.y; a1.z += v1.z; a1.w += v1.w;
                            a2.x += v2.x; a2.y += v2.y; a2.z += v2.z; a2.w += v2.w;
                            a3.x += v3.x; a3.y += v3.y; a3.z += v3.z; a3.w += v3.w;
                        }
                        for (; i < e; i++) {
                            int s0 = g_ssrc[i];
                            float4 v0 = __ldg(&xv[(size_t)s0 * 32 + lane]);
                            a1.x += v0.x; a1.y += v0.y; a1.z += v0.z; a1.w += v0.w;
                        }
                        a0.x += a1.x + a2.x + a3.x;
                        a0.y += a1.y + a2.y + a3.y;
                        a0.z += a1.z + a2.z + a3.z;
                        a0.w += a1.w + a2.w + a3.w;
                    }
                    *((float4*)&buf[lr * HSTR + lane * 4]) = a0;
                }
            }
        } else {
            // ---------------- compute warps: MLP on tile j-1 ----------------
            if (j >= 1) {
                int tile = bid + (j - 1) * G;
                int row0 = tile * TILE_R;
                float* buf = Bs[(j - 1) & 1];
                int nrows = N_NODES - row0; if (nrows > TILE_R) nrows = TILE_R;

                float acc[4][8];
#pragma unroll
                for (int r = 0; r < 4; r++)
#pragma unroll
                    for (int c = 0; c < 8; c++) acc[r][c] = 0.f;

#pragma unroll 4
                for (int k = 0; k < 128; k++) {
                    float a[4];
#pragma unroll
                    for (int r = 0; r < 4; r++) a[r] = buf[(rb + r) * HSTR + k];
                    float4 w0 = __ldg((const float4*)&W1[k * 128 + cb]);
                    float4 w1 = __ldg((const float4*)&W1[k * 128 + cb + 4]);
                    float bv[8] = {w0.x, w0.y, w0.z, w0.w, w1.x, w1.y, w1.z, w1.w};
#pragma unroll
                    for (int r = 0; r < 4; r++)
#pragma unroll
                        for (int c = 0; c < 8; c++) acc[r][c] += a[r] * bv[c];
                }

                // save h cells for MLP residual before overwriting with T
                float4 hreg[4][2];
#pragma unroll
                for (int r = 0; r < 4; r++) {
                    hreg[r][0] = *((float4*)&buf[(rb + r) * HSTR + cb]);
                    hreg[r][1] = *((float4*)&buf[(rb + r) * HSTR + cb + 4]);
                }
                asm volatile("bar.sync 1, 128;" ::: "memory");

#pragma unroll
                for (int r = 0; r < 4; r++)
#pragma unroll
                    for (int c = 0; c < 8; c++) {
                        float v = acc[r][c] + __ldg(&b1[cb + c]);
                        buf[(rb + r) * HSTR + cb + c] = fmaxf(v, 0.f);
                    }
                asm volatile("bar.sync 1, 128;" ::: "memory");

#pragma unroll
                for (int r = 0; r < 4; r++)
#pragma unroll
                    for (int c = 0; c < 8; c++) acc[r][c] = 0.f;

#pragma unroll 4
                for (int k = 0; k < 128; k++) {
                    float a[4];
#pragma unroll
                    for (int r = 0; r < 4; r++) a[r] = buf[(rb + r) * HSTR + k];
                    float4 w0 = __ldg((const float4*)&W2[k * 128 + cb]);
                    float4 w1 = __ldg((const float4*)&W2[k * 128 + cb + 4]);
                    float bv[8] = {w0.x, w0.y, w0.z, w0.w, w1.x, w1.y, w1.z, w1.w};
#pragma unroll
                    for (int r = 0; r < 4; r++)
#pragma unroll
                        for (int c = 0; c < 8; c++) acc[r][c] += a[r] * bv[c];
                }

#pragma unroll
                for (int r = 0; r < 4; r++) {
                    int row = rb + r;
                    if (row < nrows) {
                        size_t base = (size_t)(row0 + row) * HID + cb;
                        float hv[8] = {hreg[r][0].x, hreg[r][0].y, hreg[r][0].z, hreg[r][0].w,
                                       hreg[r][1].x, hreg[r][1].y, hreg[r][1].z, hreg[r][1].w};
                        float4 xi0 = __ldg((const float4*)(src + base));
                        float4 xi1 = __ldg((const float4*)(src + base + 4));
                        float xvv[8] = {xi0.x, xi0.y, xi0.z, xi0.w, xi1.x, xi1.y, xi1.z, xi1.w};
                        float o[8];
#pragma unroll
                        for (int c = 0; c < 8; c++) {
                            float v = acc[r][c] + __ldg(&b2[cb + c]);
                            if (add_h) v += hv[c];
                            o[c] = fmaxf(v, 0.f) + xvv[c];
                        }
                        *((float4*)(dstbuf + base))     = make_float4(o[0], o[1], o[2], o[3]);
                        *((float4*)(dstbuf + base + 4)) = make_float4(o[4], o[5], o[6], o[7]);
                    }
                }
            }
        }
        __syncthreads();   // epoch boundary: tile j handed to compute, buf freed
    }
}

// ---------------- mean pool over sorted batch (reads g_x — final buffer) ----------
#define POOL_CHUNK 256
__global__ void pool_kernel(const int* __restrict__ batch) {
    int d = threadIdx.x;  // 128
    int n0 = blockIdx.x * POOL_CHUNK;
    int n1 = n0 + POOL_CHUNK; if (n1 > N_NODES) n1 = N_NODES;
    int cur = batch[n0];
    float local = 0.f;
    for (int n = n0; n < n1; n++) {
        int b = batch[n];
        if (b != cur) {
            atomicAdd(&g_pool[cur * HID + d], local);
            local = 0.f; cur = b;
        }
        local += g_x[(size_t)n * HID + d];
    }
    atomicAdd(&g_pool[cur * HID + d], local);
    if (d == 0) {
        int c2 = batch[n0];
        float cl = 0.f;
        for (int n = n0; n < n1; n++) {
            int b = batch[n];
            if (b != c2) { atomicAdd(&g_cnt[c2], cl); cl = 0.f; c2 = b; }
            cl += 1.f;
        }
        atomicAdd(&g_cnt[c2], cl);
    }
}

// ---------------- classifier ----------------
__global__ void cls1_kernel(const float* __restrict__ Wc1,
                            const float* __restrict__ bc1) {
    __shared__ float Ps[128];
    int g = blockIdx.x;
    int t = threadIdx.x;
    float inv = 1.f / fmaxf(g_cnt[g], 1.f);
    Ps[t] = g_pool[g * HID + t] * inv;
    __syncthreads();
    float s = bc1[t];
#pragma unroll 4
    for (int k = 0; k < 128; k++) s += Ps[k] * __ldg(&Wc1[k * 128 + t]);
    g_cls[g * HID + t] = fmaxf(s, 0.f);
}

__global__ void cls2_kernel(const float* __restrict__ Wc2,
                            const float* __restrict__ bc2,
                            float* __restrict__ out) {
    int t = threadIdx.x;
    int g = t >> 1, c = t & 1;
    float s = bc2[c];
#pragma unroll 4
    for (int k = 0; k < 128; k++) s += g_cls[g * HID + k] * __ldg(&Wc2[k * 2 + c]);
    out[t] = s;
}

// ---------------- launch (pure kernel launches — graph-capture safe) -------------
// NOTE: never do pointer arithmetic on __device__ symbols here (host shadow trap).
extern "C" void kernel_launch(void* const* d_in, const int* in_sizes, int n_in,
                              void* d_out, int out_size) {
    const float* x     = (const float*)d_in[0];
    const int*   ei    = (const int*)d_in[1];     // int32 (JAX x64 disabled)
    const int*   batch = (const int*)d_in[2];     // int32
    const float* eps   = (const float*)d_in[3];
    const float* W1    = (const float*)d_in[4];
    const float* b1    = (const float*)d_in[5];
    const float* W2    = (const float*)d_in[6];
    const float* b2    = (const float*)d_in[7];
    const float* Wc1   = (const float*)d_in[8];
    const float* bc1   = (const float*)d_in[9];
    const float* Wc2   = (const float*)d_in[10];
    const float* bc2   = (const float*)d_in[11];
    const int* src = ei;
    const int* dst = ei + N_EDGES;

    const int nblk_scan = (N_NODES + 511) / 512;  // 196

    zero_kernel<<<(N_NODES + 255) / 256, 256>>>();
    hist_kernel<<<(N_EDGES + 255) / 256, 256>>>(dst);
    scan1_kernel<<<nblk_scan, 512>>>();
    scan2_kernel<<<1, 256>>>(nblk_scan);
    scan3_kernel<<<(N_NODES + 255) / 256, 256>>>();
    scatter_kernel<<<(N_EDGES + 255) / 256, 256>>>(src, dst);

    for (int i = 0; i < NUM_LAYERS; i++) {
        layer_kernel<<<GRID_L, 256>>>(
            x, eps,
            W1 + (size_t)i * HID * HID, b1 + (size_t)i * HID,
            W2 + (size_t)i * HID * HID, b2 + (size_t)i * HID,
            i);
    }

    pool_kernel<<<(N_NODES + POOL_CHUNK - 1) / POOL_CHUNK, 128>>>(batch);
    cls1_kernel<<<NUM_GRAPHS, 128>>>(Wc1, bc1);
    cls2_kernel<<<1, 128>>>(Wc2, bc2, (float*)d_out);
}

// round 17
// speedup vs baseline: 1.0871x; 1.0871x over previous
#include <cuda_runtime.h>
#include <cstdint>

#define N_NODES 100000
#define N_EDGES 1600000
#define HID 128
#define NUM_LAYERS 10
#define NUM_GRAPHS 64
#define NUM_CLASSES 2

// ---------------- scratch (device globals; no runtime allocation) ----------------
__device__ __align__(16) float g_x[(size_t)N_NODES * HID];
__device__ __align__(16) float g_h[(size_t)N_NODES * HID];
__device__ int   g_deg[N_NODES];
__device__ int   g_rowptr[N_NODES + 1];
__device__ int   g_fill[N_NODES];
__device__ int   g_ssrc[N_EDGES];
__device__ int   g_bsums[256];
__device__ __align__(16) float g_pool[NUM_GRAPHS * HID];
__device__ float g_cnt[NUM_GRAPHS];
__device__ __align__(16) float g_cls[NUM_GRAPHS * HID];

// ---------------- CSR build ----------------
__global__ void zero_kernel() {
    int i = blockIdx.x * blockDim.x + threadIdx.x;
    if (i < N_NODES) g_deg[i] = 0;
    if (i < NUM_GRAPHS * HID) g_pool[i] = 0.f;
    if (i < NUM_GRAPHS) g_cnt[i] = 0.f;
}

__global__ void hist_kernel(const int* __restrict__ dst) {
    int e = blockIdx.x * blockDim.x + threadIdx.x;
    if (e < N_EDGES) atomicAdd(&g_deg[dst[e]], 1);
}

__global__ void scan1_kernel() {
    __shared__ int s[512];
    int tid = threadIdx.x;
    int i = blockIdx.x * 512 + tid;
    int v = (i < N_NODES) ? g_deg[i] : 0;
    s[tid] = v;
    __syncthreads();
    for (int off = 1; off < 512; off <<= 1) {
        int add = (tid >= off) ? s[tid - off] : 0;
        __syncthreads();
        s[tid] += add;
        __syncthreads();
    }
    if (i < N_NODES) g_rowptr[i] = s[tid] - v;
    if (tid == 511) g_bsums[blockIdx.x] = s[511];
}

__global__ void scan2_kernel(int nblk) {
    __shared__ int s[256];
    int tid = threadIdx.x;
    int v = (tid < nblk) ? g_bsums[tid] : 0;
    s[tid] = v;
    __syncthreads();
    for (int off = 1; off < 256; off <<= 1) {
        int add = (tid >= off) ? s[tid - off] : 0;
        __syncthreads();
        s[tid] += add;
        __syncthreads();
    }
    if (tid < nblk) g_bsums[tid] = s[tid] - v;
}

__global__ void scan3_kernel() {
    int i = blockIdx.x * blockDim.x + threadIdx.x;
    if (i < N_NODES) {
        int rp = g_rowptr[i] + g_bsums[i >> 9];
        g_rowptr[i] = rp;
        g_fill[i] = rp;
    }
    if (i == 0) g_rowptr[N_NODES] = N_EDGES;
}

__global__ void scatter_kernel(const int* __restrict__ src,
                               const int* __restrict__ dst) {
    int e = blockIdx.x * blockDim.x + threadIdx.x;
    if (e < N_EDGES) {
        int d = dst[e];
        int p = atomicAdd(&g_fill[d], 1);
        g_ssrc[p] = src[e];
    }
}

// ---------------- per-layer aggregation: h[v] = (1+eps)*x[v] + sum_in x[u] --------
// unroll-8 main loop: 8 outstanding row loads per warp to cover L2 latency.
__global__ void aggr_kernel(const float* __restrict__ xin_ext,
                            const float* __restrict__ eps, int layer, int use_gx) {
    int gw = (blockIdx.x * blockDim.x + threadIdx.x) >> 5;
    int lane = threadIdx.x & 31;
    if (gw >= N_NODES) return;
    const float* x = use_gx ? g_x : xin_ext;
    float ep1 = 1.0f + eps[layer];
    const float4* xv = (const float4*)x;
    float4 b = __ldg(&xv[(size_t)gw * 32 + lane]);
    float4 a0 = make_float4(b.x * ep1, b.y * ep1, b.z * ep1, b.w * ep1);
    float4 a1 = make_float4(0.f, 0.f, 0.f, 0.f);
    float4 a2 = a1, a3 = a1;
    int s = g_rowptr[gw], e = g_rowptr[gw + 1];
    int i = s;
    for (; i + 8 <= e; i += 8) {
        int s0 = g_ssrc[i],     s1 = g_ssrc[i + 1];
        int s2 = g_ssrc[i + 2], s3 = g_ssrc[i + 3];
        int s4 = g_ssrc[i + 4], s5 = g_ssrc[i + 5];
        int s6 = g_ssrc[i + 6], s7 = g_ssrc[i + 7];
        float4 v0 = __ldg(&xv[(size_t)s0 * 32 + lane]);
        float4 v1 = __ldg(&xv[(size_t)s1 * 32 + lane]);
        float4 v2 = __ldg(&xv[(size_t)s2 * 32 + lane]);
        float4 v3 = __ldg(&xv[(size_t)s3 * 32 + lane]);
        float4 v4 = __ldg(&xv[(size_t)s4 * 32 + lane]);
        float4 v5 = __ldg(&xv[(size_t)s5 * 32 + lane]);
        float4 v6 = __ldg(&xv[(size_t)s6 * 32 + lane]);
        float4 v7 = __ldg(&xv[(size_t)s7 * 32 + lane]);
        a0.x += v0.x; a0.y += v0.y; a0.z += v0.z; a0.w += v0.w;
        a1.x += v1.x; a1.y += v1.y; a1.z += v1.z; a1.w += v1.w;
        a2.x += v2.x; a2.y += v2.y; a2.z += v2.z; a2.w += v2.w;
        a3.x += v3.x; a3.y += v3.y; a3.z += v3.z; a3.w += v3.w;
        a0.x += v4.x; a0.y += v4.y; a0.z += v4.z; a0.w += v4.w;
        a1.x += v5.x; a1.y += v5.y; a1.z += v5.z; a1.w += v5.w;
        a2.x += v6.x; a2.y += v6.y; a2.z += v6.z; a2.w += v6.w;
        a3.x += v7.x; a3.y += v7.y; a3.z += v7.z; a3.w += v7.w;
    }
    for (; i + 4 <= e; i += 4) {
        int s0 = g_ssrc[i], s1 = g_ssrc[i + 1], s2 = g_ssrc[i + 2], s3 = g_ssrc[i + 3];
        float4 v0 = __ldg(&xv[(size_t)s0 * 32 + lane]);
        float4 v1 = __ldg(&xv[(size_t)s1 * 32 + lane]);
        float4 v2 = __ldg(&xv[(size_t)s2 * 32 + lane]);
        float4 v3 = __ldg(&xv[(size_t)s3 * 32 + lane]);
        a0.x += v0.x; a0.y += v0.y; a0.z += v0.z; a0.w += v0.w;
        a1.x += v1.x; a1.y += v1.y; a1.z += v1.z; a1.w += v1.w;
        a2.x += v2.x; a2.y += v2.y; a2.z += v2.z; a2.w += v2.w;
        a3.x += v3.x; a3.y += v3.y; a3.z += v3.z; a3.w += v3.w;
    }
    for (; i < e; i++) {
        int s0 = g_ssrc[i];
        float4 v0 = __ldg(&xv[(size_t)s0 * 32 + lane]);
        a1.x += v0.x; a1.y += v0.y; a1.z += v0.z; a1.w += v0.w;
    }
    a0.x += a1.x + a2.x + a3.x;
    a0.y += a1.y + a2.y + a3.y;
    a0.z += a1.z + a2.z + a3.z;
    a0.w += a1.w + a2.w + a3.w;
    ((float4*)g_h)[(size_t)gw * 32 + lane] = a0;
}

// ---------------- fused MLP: g_x = relu(relu(h@W1+b1)@W2 + b2 [+h]) + xin ---------
// R6 structure; k-loop chunked by 4 with float4 LDS for A (fewer issue slots).
#define BM 64
#define HSTR 132  // padded row stride in floats (k-chunks of 4 stay 16B-aligned)

__global__ void __launch_bounds__(256)
mlp_kernel(const float* __restrict__ xin_ext,
           const float* __restrict__ W1, const float* __restrict__ b1,
           const float* __restrict__ W2, const float* __restrict__ b2,
           int add_h, int use_gx) {
    __shared__ float Bs[BM * HSTR];

    const float* xin = use_gx ? g_x : xin_ext;
    int t = threadIdx.x;
    int row0 = blockIdx.x * BM;
    int nrows = N_NODES - row0; if (nrows > BM) nrows = BM;

    // load H tile (BM x 128) into shared
    for (int i = t; i < BM * 32; i += 256) {
        int r = i >> 5, c = i & 31;
        float4 v = (r < nrows)
            ? *((const float4*)(g_h + (size_t)(row0 + r) * HID) + c)
            : make_float4(0.f, 0.f, 0.f, 0.f);
        *((float4*)&Bs[r * HSTR + c * 4]) = v;
    }
    __syncthreads();

    int tx = t & 15, ty = t >> 4;   // 16 x 16 thread grid
    int cb = tx * 8;                // 8 cols per thread
    int rb = ty * 4;                // 4 rows per thread

    float acc[4][8];
#pragma unroll
    for (int r = 0; r < 4; r++)
#pragma unroll
        for (int c = 0; c < 8; c++) acc[r][c] = 0.f;

#pragma unroll 2
    for (int k4 = 0; k4 < 32; k4++) {
        float4 a4[4];
#pragma unroll
        for (int r = 0; r < 4; r++)
            a4[r] = *((const float4*)&Bs[(rb + r) * HSTR + k4 * 4]);
#pragma unroll
        for (int kk = 0; kk < 4; kk++) {
            int k = k4 * 4 + kk;
            float4 w0 = __ldg((const float4*)&W1[k * 128 + cb]);
            float4 w1 = __ldg((const float4*)&W1[k * 128 + cb + 4]);
            float bv[8] = {w0.x, w0.y, w0.z, w0.w, w1.x, w1.y, w1.z, w1.w};
            float a[4] = {((const float*)&a4[0])[kk], ((const float*)&a4[1])[kk],
                          ((const float*)&a4[2])[kk], ((const float*)&a4[3])[kk]};
#pragma unroll
            for (int r = 0; r < 4; r++)
#pragma unroll
                for (int c = 0; c < 8; c++) acc[r][c] += a[r] * bv[c];
        }
    }
    __syncthreads();  // all GEMM1 reads of Bs done — safe to overwrite

    // write T = relu(acc + b1) into the SAME buffer
#pragma unroll
    for (int r = 0; r < 4; r++)
#pragma unroll
        for (int c = 0; c < 8; c++) {
            float v = acc[r][c] + __ldg(&b1[cb + c]);
            Bs[(rb + r) * HSTR + cb + c] = fmaxf(v, 0.f);
        }
    __syncthreads();

#pragma unroll
    for (int r = 0; r < 4; r++)
#pragma unroll
        for (int c = 0; c < 8; c++) acc[r][c] = 0.f;

#pragma unroll 2
    for (int k4 = 0; k4 < 32; k4++) {
        float4 a4[4];
#pragma unroll
        for (int r = 0; r < 4; r++)
            a4[r] = *((const float4*)&Bs[(rb + r) * HSTR + k4 * 4]);
#pragma unroll
        for (int kk = 0; kk < 4; kk++) {
            int k = k4 * 4 + kk;
            float4 w0 = __ldg((const float4*)&W2[k * 128 + cb]);
            float4 w1 = __ldg((const float4*)&W2[k * 128 + cb + 4]);
            float bv[8] = {w0.x, w0.y, w0.z, w0.w, w1.x, w1.y, w1.z, w1.w};
            float a[4] = {((const float*)&a4[0])[kk], ((const float*)&a4[1])[kk],
                          ((const float*)&a4[2])[kk], ((const float*)&a4[3])[kk]};
#pragma unroll
            for (int r = 0; r < 4; r++)
#pragma unroll
                for (int c = 0; c < 8; c++) acc[r][c] += a[r] * bv[c];
        }
    }

    // epilogue: + b2 [+ h reread] relu + xin, store
#pragma unroll
    for (int r = 0; r < 4; r++) {
        int row = rb + r;
        if (row < nrows) {
            size_t base = (size_t)(row0 + row) * HID + cb;
            float4 h0 = make_float4(0.f, 0.f, 0.f, 0.f), h1 = h0;
            if (add_h) {
                h0 = *((const float4*)(g_h + base));
                h1 = *((const float4*)(g_h + base + 4));
            }
            float hv[8] = {h0.x, h0.y, h0.z, h0.w, h1.x, h1.y, h1.z, h1.w};
            float4 xi0 = *((const float4*)(xin + base));
            float4 xi1 = *((const float4*)(xin + base + 4));
            float xv[8] = {xi0.x, xi0.y, xi0.z, xi0.w, xi1.x, xi1.y, xi1.z, xi1.w};
            float o[8];
#pragma unroll
            for (int c = 0; c < 8; c++) {
                float v = acc[r][c] + __ldg(&b2[cb + c]) + hv[c];
                o[c] = fmaxf(v, 0.f) + xv[c];
            }
            *((float4*)(g_x + base))     = make_float4(o[0], o[1], o[2], o[3]);
            *((float4*)(g_x + base + 4)) = make_float4(o[4], o[5], o[6], o[7]);
        }
    }
}

// ---------------- mean pool over sorted batch ----------------
#define POOL_CHUNK 256
__global__ void pool_kernel(const int* __restrict__ batch) {
    int d = threadIdx.x;  // 128
    int n0 = blockIdx.x * POOL_CHUNK;
    int n1 = n0 + POOL_CHUNK; if (n1 > N_NODES) n1 = N_NODES;
    int cur = batch[n0];
    float local = 0.f;
    for (int n = n0; n < n1; n++) {
        int b = batch[n];
        if (b != cur) {
            atomicAdd(&g_pool[cur * HID + d], local);
            local = 0.f; cur = b;
        }
        local += g_x[(size_t)n * HID + d];
    }
    atomicAdd(&g_pool[cur * HID + d], local);
    if (d == 0) {
        int c2 = batch[n0];
        float cl = 0.f;
        for (int n = n0; n < n1; n++) {
            int b = batch[n];
            if (b != c2) { atomicAdd(&g_cnt[c2], cl); cl = 0.f; c2 = b; }
            cl += 1.f;
        }
        atomicAdd(&g_cnt[c2], cl);
    }
}

// ---------------- classifier ----------------
__global__ void cls1_kernel(const float* __restrict__ Wc1,
                            const float* __restrict__ bc1) {
    __shared__ float Ps[128];
    int g = blockIdx.x;
    int t = threadIdx.x;
    float inv = 1.f / fmaxf(g_cnt[g], 1.f);
    Ps[t] = g_pool[g * HID + t] * inv;
    __syncthreads();
    float s = bc1[t];
#pragma unroll 4
    for (int k = 0; k < 128; k++) s += Ps[k] * __ldg(&Wc1[k * 128 + t]);
    g_cls[g * HID + t] = fmaxf(s, 0.f);
}

__global__ void cls2_kernel(const float* __restrict__ Wc2,
                            const float* __restrict__ bc2,
                            float* __restrict__ out) {
    int t = threadIdx.x;
    int g = t >> 1, c = t & 1;
    float s = bc2[c];
#pragma unroll 4
    for (int k = 0; k < 128; k++) s += g_cls[g * HID + k] * __ldg(&Wc2[k * 2 + c]);
    out[t] = s;
}

// ---------------- launch (pure kernel launches — graph-capture safe) -------------
// NOTE: never do pointer arithmetic on __device__ symbols here (host shadow trap).
extern "C" void kernel_launch(void* const* d_in, const int* in_sizes, int n_in,
                              void* d_out, int out_size) {
    const float* x     = (const float*)d_in[0];
    const int*   ei    = (const int*)d_in[1];     // int32 (JAX x64 disabled)
    const int*   batch = (const int*)d_in[2];     // int32
    const float* eps   = (const float*)d_in[3];
    const float* W1    = (const float*)d_in[4];
    const float* b1    = (const float*)d_in[5];
    const float* W2    = (const float*)d_in[6];
    const float* b2    = (const float*)d_in[7];
    const float* Wc1   = (const float*)d_in[8];
    const float* bc1   = (const float*)d_in[9];
    const float* Wc2   = (const float*)d_in[10];
    const float* bc2   = (const float*)d_in[11];
    const int* src = ei;
    const int* dst = ei + N_EDGES;

    const int nblk_scan = (N_NODES + 511) / 512;  // 196

    zero_kernel<<<(N_NODES + 255) / 256, 256>>>();
    hist_kernel<<<(N_EDGES + 255) / 256, 256>>>(dst);
    scan1_kernel<<<nblk_scan, 512>>>();
    scan2_kernel<<<1, 256>>>(nblk_scan);
    scan3_kernel<<<(N_NODES + 255) / 256, 256>>>();
    scatter_kernel<<<(N_EDGES + 255) / 256, 256>>>(src, dst);

    for (int i = 0; i < NUM_LAYERS; i++) {
        int use_gx = (i > 0) ? 1 : 0;
        aggr_kernel<<<(N_NODES + 7) / 8, 256>>>(x, eps, i, use_gx);
        mlp_kernel<<<(N_NODES + BM - 1) / BM, 256>>>(
            x,
            W1 + (size_t)i * HID * HID, b1 + (size_t)i * HID,
            W2 + (size_t)i * HID * HID, b2 + (size_t)i * HID,
            (i > 0) ? 1 : 0, use_gx);
    }

    pool_kernel<<<(N_NODES + POOL_CHUNK - 1) / POOL_CHUNK, 128>>>(batch);
    cls1_kernel<<<NUM_GRAPHS, 128>>>(Wc1, bc1);
    cls2_kernel<<<1, 128>>>(Wc2, bc2, (float*)d_out);
}